// round 3
// baseline (speedup 1.0000x reference)
#include <cuda_runtime.h>
#include <cstdint>

#define FULLMASK 0xffffffffu

// ---------------- scratch (no allocation allowed) ----------------
__device__ float g_A[256 * 16];       // A[a][j]: column j of U restricted to encoding subspace
__device__ float g_G[1024];           // G[k][i][j], 4x16x16
__device__ float g_partials[4096 * 8];// per-block {sum[4], sumsq[4]}
__device__ float g_stats[8];          // {scale[4], shift[4]}

// ---------------- quantum gates on 8 amps/lane (bits 0..2 = reg, bits 3..7 = lane) --------
template <int Q>
__device__ __forceinline__ void apply_ry(float st[8], float c, float s, int lane) {
    if constexpr (Q < 3) {
        constexpr int m = 1 << Q;
#pragma unroll
        for (int r = 0; r < 8; r++) {
            if (!(r & m)) {
                float a0 = st[r], a1 = st[r | m];
                st[r]     = c * a0 - s * a1;
                st[r | m] = s * a0 + c * a1;
            }
        }
    } else {
        constexpr int lb = 1 << (Q - 3);
        bool hi = (lane & lb) != 0;
#pragma unroll
        for (int r = 0; r < 8; r++) {
            float other = __shfl_xor_sync(FULLMASK, st[r], lb);
            st[r] = hi ? (s * other + c * st[r]) : (c * st[r] - s * other);
        }
    }
}

template <int Q>  // CNOT(ctrl=Q, tgt=Q+1)
__device__ __forceinline__ void apply_cnot(float st[8], int lane) {
    if constexpr (Q <= 1) {
        constexpr int cm = 1 << Q, tm = 2 << Q;
#pragma unroll
        for (int r = 0; r < 8; r++) {
            if ((r & cm) && !(r & tm)) {
                float t = st[r];
                st[r] = st[r | tm];
                st[r | tm] = t;
            }
        }
    } else if constexpr (Q == 2) {
        // ctrl bit 2 in-reg, tgt bit 3 = lane bit 0
#pragma unroll
        for (int r = 4; r < 8; r++) {
            st[r] = __shfl_xor_sync(FULLMASK, st[r], 1);
        }
    } else {
        constexpr int cb = 1 << (Q - 3), tb = 1 << (Q - 2);
        bool hi = (lane & cb) != 0;
#pragma unroll
        for (int r = 0; r < 8; r++) {
            float other = __shfl_xor_sync(FULLMASK, st[r], tb);
            if (hi) st[r] = other;
        }
    }
}

// -------- kernel 1: simulate fixed unitary U on the 16 encoding basis states --------
__global__ void __launch_bounds__(32, 1) sim_kernel(const float* __restrict__ params) {
    const int j = blockIdx.x;      // basis column 0..15
    const int lane = threadIdx.x;  // 0..31

    float st[8];
#pragma unroll
    for (int r = 0; r < 8; r++) st[r] = (((lane << 3) | r) == j) ? 1.f : 0.f;

    for (int layer = 0; layer < 3; layer++) {
        const float* p = params + layer * 8;
        float c, s;
        __sincosf(0.5f * p[0], &s, &c); apply_ry<0>(st, c, s, lane);
        __sincosf(0.5f * p[1], &s, &c); apply_ry<1>(st, c, s, lane);
        __sincosf(0.5f * p[2], &s, &c); apply_ry<2>(st, c, s, lane);
        __sincosf(0.5f * p[3], &s, &c); apply_ry<3>(st, c, s, lane);
        __sincosf(0.5f * p[4], &s, &c); apply_ry<4>(st, c, s, lane);
        __sincosf(0.5f * p[5], &s, &c); apply_ry<5>(st, c, s, lane);
        __sincosf(0.5f * p[6], &s, &c); apply_ry<6>(st, c, s, lane);
        __sincosf(0.5f * p[7], &s, &c); apply_ry<7>(st, c, s, lane);
        apply_cnot<0>(st, lane);
        apply_cnot<1>(st, lane);
        apply_cnot<2>(st, lane);
        apply_cnot<3>(st, lane);
        apply_cnot<4>(st, lane);
        apply_cnot<5>(st, lane);
        apply_cnot<6>(st, lane);
    }

#pragma unroll
    for (int r = 0; r < 8; r++) g_A[((lane << 3) | r) * 16 + j] = st[r];
}

// -------- kernel 2: G[k][i][j] = sum_a w_k(a) * A[a][i] * A[a][j] --------
__global__ void __launch_bounds__(64, 1) gmat_kernel(const float* __restrict__ W) {
    __shared__ float As[256 * 16];
    __shared__ float wt[256];

    const int tid = threadIdx.x;               // 0..63
    const int e = blockIdx.x * 64 + tid;       // 0..1023
    const int k = e >> 8;                      // constant per block
    const int i = (e >> 4) & 15;
    const int jj = e & 15;

    float4* As4 = reinterpret_cast<float4*>(As);
    const float4* gA4 = reinterpret_cast<const float4*>(g_A);
#pragma unroll
    for (int t = tid; t < 1024; t += 64) As4[t] = gA4[t];

    float wk[8];
#pragma unroll
    for (int w = 0; w < 8; w++) wk[w] = W[k * 8 + w];
#pragma unroll
    for (int a = tid; a < 256; a += 64) {
        float t = 0.f;
#pragma unroll
        for (int w = 0; w < 8; w++) t += ((a >> w) & 1) ? -wk[w] : wk[w];
        wt[a] = t;
    }
    __syncthreads();

    float acc = 0.f;
#pragma unroll 8
    for (int a = 0; a < 256; a++)
        acc += wt[a] * As[a * 16 + i] * As[a * 16 + jj];
    g_G[e] = acc;
}

// -------- kernel 3: per-batch pooled -> v -> out_k = v^T G_k v + b_k; write + partial sums -----
__global__ void __launch_bounds__(256) main_kernel(const float* __restrict__ x,
                                                   const float* __restrict__ bias,
                                                   float* __restrict__ out,
                                                   int B) {
    __shared__ float Gs[1024];
    __shared__ float red[8][8];

    const int tid = threadIdx.x;
    reinterpret_cast<float4*>(Gs)[tid] = reinterpret_cast<const float4*>(g_G)[tid];
    __syncthreads();

    const int b = blockIdx.x * 256 + tid;
    float o0 = 0.f, o1 = 0.f, o2 = 0.f, o3 = 0.f;

    if (b < B) {
        const float4* xp = reinterpret_cast<const float4*>(x + (size_t)b * 144);
        float p00 = 0.f, p01 = 0.f, p10 = 0.f, p11 = 0.f;
#pragma unroll
        for (int r = 0; r < 12; r++) {
            float4 f0 = xp[3 * r + 0];
            float4 f1 = xp[3 * r + 1];
            float4 f2 = xp[3 * r + 2];
            float left  = f0.x + f0.y + f0.z + f0.w + f1.x + f1.y;
            float right = f1.z + f1.w + f2.x + f2.y + f2.z + f2.w;
            if (r < 6) { p00 += left; p01 += right; }
            else       { p10 += left; p11 += right; }
        }
        const float inv72 = 1.0f / 72.0f;  // (sum/36) / 2
        float c0, s0, c1, s1, c2, s2, c3, s3;
        __sincosf(p00 * inv72, &s0, &c0);
        __sincosf(p01 * inv72, &s1, &c1);
        __sincosf(p10 * inv72, &s2, &c2);
        __sincosf(p11 * inv72, &s3, &c3);

        float t01[4] = {c0 * c1, s0 * c1, c0 * s1, s0 * s1};
        float t23[4] = {c2 * c3, s2 * c3, c2 * s3, s2 * s3};
        float v[16];
#pragma unroll
        for (int j = 0; j < 16; j++) v[j] = t01[j & 3] * t23[j >> 2];

        float o[4];
#pragma unroll
        for (int k = 0; k < 4; k++) {
            float acc = __ldg(bias + k);
#pragma unroll
            for (int i = 0; i < 16; i++) {
                const float4* Gr = reinterpret_cast<const float4*>(Gs + k * 256 + i * 16);
                float ti = 0.f;
#pragma unroll
                for (int j4 = 0; j4 < 4; j4++) {
                    float4 g = Gr[j4];
                    ti += g.x * v[4 * j4 + 0] + g.y * v[4 * j4 + 1]
                        + g.z * v[4 * j4 + 2] + g.w * v[4 * j4 + 3];
                }
                acc += v[i] * ti;
            }
            o[k] = acc;
        }
        o0 = o[0]; o1 = o[1]; o2 = o[2]; o3 = o[3];
        reinterpret_cast<float4*>(out)[b] = make_float4(o0, o1, o2, o3);
    }

    // deterministic block reduction of {sum, sumsq}
    float vals[8] = {o0, o1, o2, o3, o0 * o0, o1 * o1, o2 * o2, o3 * o3};
    const int lane = tid & 31, wid = tid >> 5;
#pragma unroll
    for (int off = 16; off > 0; off >>= 1) {
#pragma unroll
        for (int u = 0; u < 8; u++)
            vals[u] += __shfl_down_sync(FULLMASK, vals[u], off);
    }
    if (lane == 0) {
#pragma unroll
        for (int u = 0; u < 8; u++) red[wid][u] = vals[u];
    }
    __syncthreads();
    if (tid < 8) {
        float t = 0.f;
#pragma unroll
        for (int w = 0; w < 8; w++) t += red[w][tid];
        g_partials[blockIdx.x * 8 + tid] = t;
    }
}

// -------- kernel 4: reduce partials -> per-feature scale/shift --------
__global__ void __launch_bounds__(256) stats_kernel(const float* __restrict__ gamma,
                                                    const float* __restrict__ beta,
                                                    int nblocks, int B) {
    __shared__ float red[8][8];
    __shared__ float fin[8];
    const int tid = threadIdx.x;

    float acc[8] = {0.f, 0.f, 0.f, 0.f, 0.f, 0.f, 0.f, 0.f};
    for (int t = tid; t < nblocks; t += 256) {
#pragma unroll
        for (int u = 0; u < 8; u++) acc[u] += g_partials[t * 8 + u];
    }
    const int lane = tid & 31, wid = tid >> 5;
#pragma unroll
    for (int off = 16; off > 0; off >>= 1) {
#pragma unroll
        for (int u = 0; u < 8; u++)
            acc[u] += __shfl_down_sync(FULLMASK, acc[u], off);
    }
    if (lane == 0) {
#pragma unroll
        for (int u = 0; u < 8; u++) red[wid][u] = acc[u];
    }
    __syncthreads();
    if (tid < 8) {
        float t = 0.f;
#pragma unroll
        for (int w = 0; w < 8; w++) t += red[w][tid];
        fin[tid] = t;
    }
    __syncthreads();
    if (tid < 4) {
        float invB = 1.0f / (float)B;
        float mean = fin[tid] * invB;
        float var  = fin[tid + 4] * invB - mean * mean;
        float scale = gamma[tid] * rsqrtf(var + 1e-5f);
        g_stats[tid]     = scale;
        g_stats[tid + 4] = beta[tid] - scale * mean;
    }
}

// -------- kernel 5: in-place batchnorm affine --------
__global__ void __launch_bounds__(256) norm_kernel(float4* __restrict__ out, int B) {
    const int b = blockIdx.x * 256 + threadIdx.x;
    if (b < B) {
        float4 o = out[b];
        o.x = o.x * g_stats[0] + g_stats[4];
        o.y = o.y * g_stats[1] + g_stats[5];
        o.z = o.z * g_stats[2] + g_stats[6];
        o.w = o.w * g_stats[3] + g_stats[7];
        out[b] = o;
    }
}

extern "C" void kernel_launch(void* const* d_in, const int* in_sizes, int n_in,
                              void* d_out, int out_size) {
    const float* x      = (const float*)d_in[0];
    const float* params = (const float*)d_in[1];
    const float* W      = (const float*)d_in[2];
    const float* bias   = (const float*)d_in[3];
    const float* gamma  = (const float*)d_in[4];
    const float* beta   = (const float*)d_in[5];

    const int B = in_sizes[0] / 144;
    const int nblocks = (B + 255) / 256;

    sim_kernel<<<16, 32>>>(params);
    gmat_kernel<<<16, 64>>>(W);
    main_kernel<<<nblocks, 256>>>(x, bias, (float*)d_out, B);
    stats_kernel<<<1, 256>>>(gamma, beta, nblocks, B);
    norm_kernel<<<nblocks, 256>>>((float4*)d_out, B);
}

// round 4
// speedup vs baseline: 1.3017x; 1.3017x over previous
#include <cuda_runtime.h>
#include <cstdint>

#define FULLMASK 0xffffffffu
#define NWORK 128
#define TILE 512

// ---------------- global scratch (no allocation allowed) ----------------
__device__ float g_Gp[136 * 4];        // packed symmetric G'[pair][k] (off-diag pre-doubled)
__device__ float g_partials[NWORK * 8];// per-worker-block {sum[4], sumsq[4]}
__device__ float g_stats[8];           // {scale[4], shift[4]}
__device__ int   g_sync[4];            // [0]=Gp ready, [1]=counter, [2]=stats flag

// ---------------- quantum gates: 8 amps/lane (bits 0..2 = reg, 3..7 = lane) ----------------
template <int Q>
__device__ __forceinline__ void apply_ry(float st[8], float c, float s, int lane) {
    if constexpr (Q < 3) {
        constexpr int m = 1 << Q;
#pragma unroll
        for (int r = 0; r < 8; r++) {
            if (!(r & m)) {
                float a0 = st[r], a1 = st[r | m];
                st[r]     = c * a0 - s * a1;
                st[r | m] = s * a0 + c * a1;
            }
        }
    } else {
        constexpr int lb = 1 << (Q - 3);
        bool hi = (lane & lb) != 0;
#pragma unroll
        for (int r = 0; r < 8; r++) {
            float other = __shfl_xor_sync(FULLMASK, st[r], lb);
            st[r] = hi ? (s * other + c * st[r]) : (c * st[r] - s * other);
        }
    }
}

template <int Q>  // CNOT(ctrl=Q, tgt=Q+1)
__device__ __forceinline__ void apply_cnot(float st[8], int lane) {
    if constexpr (Q <= 1) {
        constexpr int cm = 1 << Q, tm = 2 << Q;
#pragma unroll
        for (int r = 0; r < 8; r++) {
            if ((r & cm) && !(r & tm)) {
                float t = st[r]; st[r] = st[r | tm]; st[r | tm] = t;
            }
        }
    } else if constexpr (Q == 2) {
#pragma unroll
        for (int r = 4; r < 8; r++) st[r] = __shfl_xor_sync(FULLMASK, st[r], 1);
    } else {
        constexpr int cb = 1 << (Q - 3), tb = 1 << (Q - 2);
        bool hi = (lane & cb) != 0;
#pragma unroll
        for (int r = 0; r < 8; r++) {
            float other = __shfl_xor_sync(FULLMASK, st[r], tb);
            if (hi) st[r] = other;
        }
    }
}

__global__ void reset_kernel() { g_sync[0] = 0; g_sync[1] = 0; g_sync[2] = 0; }

__global__ void __launch_bounds__(256) fused_kernel(
    const float* __restrict__ x, const float* __restrict__ params,
    const float* __restrict__ W, const float* __restrict__ bias,
    const float* __restrict__ gamma, const float* __restrict__ beta,
    float* __restrict__ out, int B)
{
    // block 0 setup scratch (36 KB): [0:4096)=A^T[j][a] / red, [4096:8192)=A[a][j], [8192:9216)=wt4 / G
    __shared__ __align__(16) float s_buf[9216];
    // worker scratch (~10.7 KB)
    __shared__ float4 pool4[TILE];
    __shared__ float4 Gp_s[136];
    __shared__ float  red_s[8][8];
    __shared__ float  fin_s[8];
    __shared__ float  stats_s[8];
    __shared__ int    last_s;

    const int tid  = threadIdx.x;
    const int lane = tid & 31;
    const int wid  = tid >> 5;

    if (blockIdx.x == 0) {
        // ================= SETUP BLOCK =================
        float* s_At = s_buf;            // A^T: [j*256 + a], then reused as red[256][16]
        float* s_A  = s_buf + 4096;     // A:   [a*16 + j]
        float* s_W1 = s_buf + 8192;     // wt4[a] float4, then G[k*256+i*16+j]

        // ---- sim: 8 warps, 2 basis columns each ----
#pragma unroll
        for (int half = 0; half < 2; half++) {
            const int j = wid + half * 8;
            float st[8];
#pragma unroll
            for (int r = 0; r < 8; r++) st[r] = (((lane << 3) | r) == j) ? 1.f : 0.f;
            for (int layer = 0; layer < 3; layer++) {
                const float* p = params + layer * 8;
                float c, s;
                __sincosf(0.5f * p[0], &s, &c); apply_ry<0>(st, c, s, lane);
                __sincosf(0.5f * p[1], &s, &c); apply_ry<1>(st, c, s, lane);
                __sincosf(0.5f * p[2], &s, &c); apply_ry<2>(st, c, s, lane);
                __sincosf(0.5f * p[3], &s, &c); apply_ry<3>(st, c, s, lane);
                __sincosf(0.5f * p[4], &s, &c); apply_ry<4>(st, c, s, lane);
                __sincosf(0.5f * p[5], &s, &c); apply_ry<5>(st, c, s, lane);
                __sincosf(0.5f * p[6], &s, &c); apply_ry<6>(st, c, s, lane);
                __sincosf(0.5f * p[7], &s, &c); apply_ry<7>(st, c, s, lane);
                apply_cnot<0>(st, lane); apply_cnot<1>(st, lane);
                apply_cnot<2>(st, lane); apply_cnot<3>(st, lane);
                apply_cnot<4>(st, lane); apply_cnot<5>(st, lane);
                apply_cnot<6>(st, lane);
            }
            float4* dst = reinterpret_cast<float4*>(&s_At[j * 256 + lane * 8]);
            dst[0] = make_float4(st[0], st[1], st[2], st[3]);
            dst[1] = make_float4(st[4], st[5], st[6], st[7]);
        }

        // ---- wt4[a] = (sum_w ±W[k][w]) for k=0..3 ----
        {
            const int a = tid;
            float4 wt = make_float4(0.f, 0.f, 0.f, 0.f);
#pragma unroll
            for (int w = 0; w < 8; w++) {
                float sgn = ((a >> w) & 1) ? -1.f : 1.f;
                wt.x += sgn * __ldg(W + 0 * 8 + w);
                wt.y += sgn * __ldg(W + 1 * 8 + w);
                wt.z += sgn * __ldg(W + 2 * 8 + w);
                wt.w += sgn * __ldg(W + 3 * 8 + w);
            }
            reinterpret_cast<float4*>(s_W1)[a] = wt;
        }
        __syncthreads();

        // ---- transpose A^T -> A[a][j] ----
        {
            const int a = tid;
#pragma unroll
            for (int j4 = 0; j4 < 4; j4++) {
                float4 v = make_float4(s_At[(4 * j4 + 0) * 256 + a],
                                       s_At[(4 * j4 + 1) * 256 + a],
                                       s_At[(4 * j4 + 2) * 256 + a],
                                       s_At[(4 * j4 + 3) * 256 + a]);
                reinterpret_cast<float4*>(s_A)[a * 4 + j4] = v;
            }
        }
        __syncthreads();

        // ---- G accumulation: thread=(item 0..63, chunk 0..3), item=(i, j4) ----
        float acc[16];
#pragma unroll
        for (int u = 0; u < 16; u++) acc[u] = 0.f;
        {
            const int item = tid & 63, chunk = tid >> 6;
            const int i = item >> 2, j4 = item & 3;
            const int a0 = chunk * 64;
#pragma unroll 4
            for (int a = a0; a < a0 + 64; a++) {
                float  Ai = s_A[a * 16 + i];
                float4 Aj = reinterpret_cast<const float4*>(s_A)[a * 4 + j4];
                float4 w4 = reinterpret_cast<const float4*>(s_W1)[a];
                float t0 = Ai * Aj.x, t1 = Ai * Aj.y, t2 = Ai * Aj.z, t3 = Ai * Aj.w;
                acc[0]  += w4.x * t0; acc[1]  += w4.x * t1; acc[2]  += w4.x * t2; acc[3]  += w4.x * t3;
                acc[4]  += w4.y * t0; acc[5]  += w4.y * t1; acc[6]  += w4.y * t2; acc[7]  += w4.y * t3;
                acc[8]  += w4.z * t0; acc[9]  += w4.z * t1; acc[10] += w4.z * t2; acc[11] += w4.z * t3;
                acc[12] += w4.w * t0; acc[13] += w4.w * t1; acc[14] += w4.w * t2; acc[15] += w4.w * t3;
            }
        }
        __syncthreads();   // s_At reads done; reuse as red
#pragma unroll
        for (int u4 = 0; u4 < 4; u4++)
            reinterpret_cast<float4*>(s_At)[tid * 4 + u4] =
                make_float4(acc[u4 * 4 + 0], acc[u4 * 4 + 1], acc[u4 * 4 + 2], acc[u4 * 4 + 3]);
        __syncthreads();

        // ---- chunk-reduce -> G into s_W1 (wt dead) ----
        {
            const int item = tid >> 2, u4 = tid & 3;  // u4 == k
            float4 s = make_float4(0.f, 0.f, 0.f, 0.f);
#pragma unroll
            for (int c = 0; c < 4; c++) {
                float4 r = reinterpret_cast<const float4*>(s_At)[(item + 64 * c) * 4 + u4];
                s.x += r.x; s.y += r.y; s.z += r.z; s.w += r.w;
            }
            const int i = item >> 2, jb = (item & 3) * 4;
            float* Gk = &s_W1[u4 * 256 + i * 16 + jb];
            Gk[0] = s.x; Gk[1] = s.y; Gk[2] = s.z; Gk[3] = s.w;
        }
        __syncthreads();

        // ---- pack symmetric upper-tri (off-diag x2) -> g_Gp[pair*4+k] ----
        if (tid < 128) {
            const int k = tid >> 5, ln = tid & 31;
            int pair = 0;
#pragma unroll
            for (int i = 0; i < 16; i++)
#pragma unroll
                for (int j = i; j < 16; j++) {
                    if ((pair & 31) == ln)
                        g_Gp[pair * 4 + k] = (i == j ? 1.f : 2.f) * s_W1[k * 256 + i * 16 + j];
                    pair++;
                }
        }
        __threadfence();
        __syncthreads();
        if (tid == 0) atomicExch(&g_sync[0], 1);
        return;   // setup block exits; does not join stats
    }

    // ================= WORKER BLOCKS =================
    const int wbid = blockIdx.x - 1;
    const int sub  = lane & 3;
    const float inv72 = 1.0f / 72.0f;

    const float b0 = __ldg(bias + 0), b1 = __ldg(bias + 1),
                b2 = __ldg(bias + 2), b3 = __ldg(bias + 3);

    float sum0 = 0.f, sum1 = 0.f, sum2 = 0.f, sum3 = 0.f;
    float sq0 = 0.f, sq1 = 0.f, sq2 = 0.f, sq3 = 0.f;
    bool gp_loaded = false;

    for (int base = wbid * TILE; base < B; base += NWORK * TILE) {
        // ---- coalesced pooling: 4 lanes per element, 64B chunks ----
#pragma unroll 1
        for (int rd = 0; rd < TILE / 64; rd++) {
            const int el = rd * 64 + wid * 8 + (lane >> 2);
            const int e = base + el;
            float pTL = 0.f, pTR = 0.f, pBL = 0.f, pBR = 0.f;
            if (e < B) {
                const float4* xp = reinterpret_cast<const float4*>(x) + (size_t)e * 36;
#pragma unroll
                for (int i = 0; i < 9; i++) {
                    const int q = sub + 4 * i;
                    float4 f = xp[q];
                    const int c = q % 3;
                    float s2a = f.x + f.y, s2b = f.z + f.w, s4 = s2a + s2b;
                    float L = (c == 0) ? s4 : ((c == 1) ? s2a : 0.f);
                    float R = (c == 2) ? s4 : ((c == 1) ? s2b : 0.f);
                    bool top = q < 18;
                    pTL += top ? L : 0.f; pBL += top ? 0.f : L;
                    pTR += top ? R : 0.f; pBR += top ? 0.f : R;
                }
            }
#pragma unroll
            for (int off = 1; off <= 2; off <<= 1) {
                pTL += __shfl_xor_sync(FULLMASK, pTL, off);
                pTR += __shfl_xor_sync(FULLMASK, pTR, off);
                pBL += __shfl_xor_sync(FULLMASK, pBL, off);
                pBR += __shfl_xor_sync(FULLMASK, pBR, off);
            }
            if (sub == 0) pool4[el] = make_float4(pTL, pTR, pBL, pBR);
        }
        __syncthreads();

        if (!gp_loaded) {
            if (tid == 0) {
                while (((volatile int*)g_sync)[0] == 0) {}
                __threadfence();
            }
            __syncthreads();
            if (tid < 136) Gp_s[tid] = reinterpret_cast<const float4*>(g_Gp)[tid];
            __syncthreads();
            gp_loaded = true;
        }

        // ---- quadratic forms: thread handles local elems 2*tid, 2*tid+1 ----
#pragma unroll
        for (int h = 0; h < 2; h++) {
            const int el = 2 * tid + h;
            const int e = base + el;
            if (e < B) {
                float4 p = pool4[el];
                float c0, s0, c1, s1, c2, s2, c3, s3;
                __sincosf(p.x * inv72, &s0, &c0);
                __sincosf(p.y * inv72, &s1, &c1);
                __sincosf(p.z * inv72, &s2, &c2);
                __sincosf(p.w * inv72, &s3, &c3);
                float t01[4] = {c0 * c1, s0 * c1, c0 * s1, s0 * s1};
                float t23[4] = {c2 * c3, s2 * c3, c2 * s3, s2 * s3};
                float v[16];
#pragma unroll
                for (int j = 0; j < 16; j++) v[j] = t01[j & 3] * t23[j >> 2];

                float a0 = b0, a1 = b1, a2 = b2, a3 = b3;
                int pair = 0;
#pragma unroll
                for (int i = 0; i < 16; i++)
#pragma unroll
                    for (int j = i; j < 16; j++) {
                        float4 g = Gp_s[pair++];
                        float pv = v[i] * v[j];
                        a0 += g.x * pv; a1 += g.y * pv; a2 += g.z * pv; a3 += g.w * pv;
                    }
                reinterpret_cast<float4*>(out)[e] = make_float4(a0, a1, a2, a3);
                sum0 += a0; sum1 += a1; sum2 += a2; sum3 += a3;
                sq0 += a0 * a0; sq1 += a1 * a1; sq2 += a2 * a2; sq3 += a3 * a3;
            }
        }
        __syncthreads();  // pool4 reuse
    }

    // ---- block reduction of {sum, sumsq} (deterministic) ----
    {
        float vals[8] = {sum0, sum1, sum2, sum3, sq0, sq1, sq2, sq3};
#pragma unroll
        for (int off = 16; off > 0; off >>= 1)
#pragma unroll
            for (int u = 0; u < 8; u++)
                vals[u] += __shfl_down_sync(FULLMASK, vals[u], off);
        if (lane == 0)
#pragma unroll
            for (int u = 0; u < 8; u++) red_s[wid][u] = vals[u];
    }
    __syncthreads();
    if (tid < 8) {
        float t = 0.f;
#pragma unroll
        for (int w = 0; w < 8; w++) t += red_s[w][tid];
        g_partials[wbid * 8 + tid] = t;
    }
    __threadfence();
    if (tid == 0) {
        int old = atomicAdd(&g_sync[1], 1);
        last_s = (old == NWORK - 1);
    }
    __syncthreads();

    if (last_s) {
        if (wid < 8) {
            float a = 0.f;
#pragma unroll
            for (int c = 0; c < NWORK / 32; c++)
                a += g_partials[(lane + 32 * c) * 8 + wid];
#pragma unroll
            for (int off = 16; off > 0; off >>= 1)
                a += __shfl_down_sync(FULLMASK, a, off);
            if (lane == 0) fin_s[wid] = a;
        }
        __syncthreads();
        if (tid < 4) {
            float invB = 1.0f / (float)B;
            float mean = fin_s[tid] * invB;
            float var  = fin_s[tid + 4] * invB - mean * mean;
            float sc = __ldg(gamma + tid) * rsqrtf(var + 1e-5f);
            g_stats[tid]     = sc;
            g_stats[tid + 4] = __ldg(beta + tid) - sc * mean;
            __threadfence();
        }
        __syncthreads();
        if (tid == 0) atomicExch(&g_sync[2], 1);
    }

    // ---- wait for stats, then in-place normalize own elements ----
    if (tid == 0) {
        while (((volatile int*)g_sync)[2] == 0) {}
        __threadfence();
    }
    __syncthreads();
    if (tid < 8) stats_s[tid] = ((volatile float*)g_stats)[tid];
    __syncthreads();

    for (int base = wbid * TILE; base < B; base += NWORK * TILE) {
#pragma unroll
        for (int h = 0; h < 2; h++) {
            const int e = base + 2 * tid + h;
            if (e < B) {
                float4 o = reinterpret_cast<float4*>(out)[e];
                o.x = o.x * stats_s[0] + stats_s[4];
                o.y = o.y * stats_s[1] + stats_s[5];
                o.z = o.z * stats_s[2] + stats_s[6];
                o.w = o.w * stats_s[3] + stats_s[7];
                reinterpret_cast<float4*>(out)[e] = o;
            }
        }
    }
}

extern "C" void kernel_launch(void* const* d_in, const int* in_sizes, int n_in,
                              void* d_out, int out_size) {
    const float* x      = (const float*)d_in[0];
    const float* params = (const float*)d_in[1];
    const float* W      = (const float*)d_in[2];
    const float* bias   = (const float*)d_in[3];
    const float* gamma  = (const float*)d_in[4];
    const float* beta   = (const float*)d_in[5];

    const int B = in_sizes[0] / 144;

    reset_kernel<<<1, 1>>>();
    fused_kernel<<<NWORK + 1, 256>>>(x, params, W, bias, gamma, beta, (float*)d_out, B);
}